// round 11
// baseline (speedup 1.0000x reference)
#include <cuda_runtime.h>

#define NTAGS    1024
#define NCTA     128
#define TPB      256
#define WARPS    8
#define TSTEPS   65536
#define SPIN_CAP (1u << 20)   // poll watchdog (~0.1s worst case)
#define VCAP     (1u << 16)   // verify watchdog

// Persistent device state.
// g_ab[pb][i]  = {f32 P_i, u32 tag} where alpha_i = log(P_i) + m_c(i)
// g_rep[pb][c] = {f32 m_c, u32 tag}: producer CTA c's exp-offset + readiness
__device__ __align__(16) unsigned long long g_ab[2][NTAGS];
__device__ __align__(16) unsigned long long g_rep[2][NCTA];
__device__ unsigned g_gen = 0;   // bumped once per launch (replay-safe tags)

__device__ __forceinline__ unsigned long long ld_rlx64(const unsigned long long* p) {
    unsigned long long v;
    asm volatile("ld.relaxed.gpu.global.b64 %0, [%1];" : "=l"(v) : "l"(p));
    return v;
}
__device__ __forceinline__ void st_rlx64(unsigned long long* p, unsigned long long v) {
    asm volatile("st.relaxed.gpu.global.b64 [%0], %1;" :: "l"(p), "l"(v) : "memory");
}
__device__ __forceinline__ unsigned long long pack_av(float a, unsigned tag) {
    return ((unsigned long long)tag << 32) | (unsigned long long)__float_as_uint(a);
}
__device__ __forceinline__ float    val_of(unsigned long long q) { return __uint_as_float((unsigned)q); }
__device__ __forceinline__ unsigned tag_of(unsigned long long q) { return (unsigned)(q >> 32); }

__global__ void __launch_bounds__(TPB, 1)
crf_kernel(const float* __restrict__ unary,
           const float* __restrict__ trans,
           const int*   __restrict__ start_p,
           const int*   __restrict__ end_p,
           float*       __restrict__ out)
{
    const int tid  = threadIdx.x;
    const int lane = tid & 31;
    const int w    = tid >> 5;           // 8 warps
    const int cta  = blockIdx.x;
    const int row  = cta * WARPS + w;    // this warp's tag row

    __shared__ float sx[NTAGS];          // sx_j = exp(alpha_j - m) = P_j * f_c(j)
    __shared__ float s_f[NCTA];          // per-producer rescale factors
    __shared__ float s_a[2][WARPS];      // this CTA's P values (for stale max)
    __shared__ int   s_bail;

    const unsigned gen = g_gen;          // stream-ordered across graph replays
    // tag(step s) = gen*65536 + s + 1   (never 0, unique across replays)

    if (tid == 0) s_bail = 0;

    // ---- E row in registers: warp w owns row `row`, lane owns cols {lane+32k}
    float E[32];
    #pragma unroll
    for (int k = 0; k < 32; k++)
        E[k] = __expf(__ldg(&trans[(size_t)row * NTAGS + lane + 32 * k]));

    float u_next = 0.0f, eu = 1.0f;      // lane0-only: next unary and exp(unary)
    float m_hist0 = 0.0f, m_hist1 = 0.0f;// own m from two steps back, per parity

    // ---- Step 0: alpha_0 = trans[:,start] + u_0; publish P = exp(alpha_0), m=0
    if (lane == 0) {
        const int sidx = *start_p;
        const float a0 = __ldg(&trans[(size_t)row * NTAGS + sidx]) + __ldg(&unary[row]);
        const float P0 = __expf(a0);     // |a0| small, safe
        s_a[0][w] = P0; s_a[1][w] = P0;  // P0 stands in for step -1 at t=1,2
        st_rlx64(&g_ab[0][row], pack_av(P0, gen * 65536u + 1u));
        if (w == WARPS - 1) st_rlx64(&g_rep[0][cta], pack_av(0.0f, gen * 65536u + 1u));
        u_next = __ldcs(&unary[(size_t)NTAGS + row]);
        eu = __expf(u_next);
    }
    __syncthreads();

    // ---- Main scan -------------------------------------------------------
    for (int t = 1; t < TSTEPS; t++) {
        const int pb = (t - 1) & 1;      // buffer holding step t-1
        const int b  = t & 1;

        // Own exp offset, 2 steps stale:
        //   m(t) = max own alpha(t-2) + 30 = log(max own P(t-2)) + m(t-2) + 30
        float maxP = s_a[b][0];
        #pragma unroll
        for (int r = 1; r < WARPS; r++) maxP = fmaxf(maxP, s_a[b][r]);
        const float mref = b ? m_hist1 : m_hist0;
        const float m = __logf(maxP) + mref + 30.0f;
        if (b) m_hist1 = m; else m_hist0 = m;

        const unsigned want = gen * 65536u + (unsigned)t;   // tag of step t-1

        // NARROW poll: warp 0 spins on the 128 rep words, builds factors.
        if (w == 0) {
            unsigned long long r0, r1, r2, r3; unsigned spins = 0;
            for (;;) {
                r0 = ld_rlx64(&g_rep[pb][lane]);
                r1 = ld_rlx64(&g_rep[pb][lane + 32]);
                r2 = ld_rlx64(&g_rep[pb][lane + 64]);
                r3 = ld_rlx64(&g_rep[pb][lane + 96]);
                if (((tag_of(r0) ^ want) | (tag_of(r1) ^ want) |
                     (tag_of(r2) ^ want) | (tag_of(r3) ^ want)) == 0u) break;
                if (++spins > SPIN_CAP) { s_bail = 1; break; }
            }
            s_f[lane]      = __expf(val_of(r0) - m);
            s_f[lane + 32] = __expf(val_of(r1) - m);
            s_f[lane + 64] = __expf(val_of(r2) - m);
            s_f[lane + 96] = __expf(val_of(r3) - m);
        }
        __syncthreads();                 // bar1: detection done, factors staged
        if (s_bail) break;

        // WIDE load exactly once, self-verifying (retries = rare stragglers).
        const unsigned long long* src = g_ab[pb];
        unsigned long long q0 = ld_rlx64(src + tid);
        unsigned long long q1 = ld_rlx64(src + tid + 256);
        unsigned long long q2 = ld_rlx64(src + tid + 512);
        unsigned long long q3 = ld_rlx64(src + tid + 768);
        {
            unsigned vs = 0;
            while (((tag_of(q0) ^ want) | (tag_of(q1) ^ want) |
                    (tag_of(q2) ^ want) | (tag_of(q3) ^ want)) != 0u) {
                q0 = ld_rlx64(src + tid);       q1 = ld_rlx64(src + tid + 256);
                q2 = ld_rlx64(src + tid + 512); q3 = ld_rlx64(src + tid + 768);
                if (++vs > VCAP) { s_bail = 1; break; }
            }
        }
        // Stage: one FMUL per element (exp eliminated from this path).
        sx[tid]       = val_of(q0) * s_f[tid >> 3];
        sx[tid + 256] = val_of(q1) * s_f[32 + (tid >> 3)];
        sx[tid + 512] = val_of(q2) * s_f[64 + (tid >> 3)];
        sx[tid + 768] = val_of(q3) * s_f[96 + (tid >> 3)];
        __syncthreads();                 // bar2: sx staged (also bail broadcast)
        if (s_bail) break;

        // Row stage: warp w computes row `row` over all 1024 cols.
        float a0 = 0.f, a1 = 0.f, a2 = 0.f, a3 = 0.f;
        #pragma unroll
        for (int k = 0; k < 32; k += 4) {
            a0 = fmaf(E[k + 0], sx[lane + 32 * (k + 0)], a0);
            a1 = fmaf(E[k + 1], sx[lane + 32 * (k + 1)], a1);
            a2 = fmaf(E[k + 2], sx[lane + 32 * (k + 2)], a2);
            a3 = fmaf(E[k + 3], sx[lane + 32 * (k + 3)], a3);
        }
        float S = (a0 + a1) + (a2 + a3);
        #pragma unroll
        for (int msk = 16; msk >= 1; msk >>= 1)
            S += __shfl_xor_sync(0xffffffffu, S, msk);

        if (lane == 0) {
            const float P = S * eu;      // alpha(t) = log(P) + m ; no log here!
            s_a[b][w] = P;
            st_rlx64(&g_ab[b][row], pack_av(P, want + 1u));
            if (w == WARPS - 1) st_rlx64(&g_rep[b][cta], pack_av(m, want + 1u));
            const int tn = (t + 1 < TSTEPS) ? t + 1 : t;
            u_next = __ldcs(&unary[(size_t)tn * NTAGS + row]);
            eu = __expf(u_next);
        }
        // next iteration's bar1 provides all remaining ordering
    }

    // ---- Terminal logsumexp (CTA 0) -------------------------------------
    if (cta == 0) {
        const unsigned want = gen * 65536u + (unsigned)TSTEPS;  // tag of T-1
        const unsigned long long* src = g_ab[(TSTEPS - 1) & 1];
        const unsigned long long* rp  = g_rep[(TSTEPS - 1) & 1];

        unsigned long long q0 = ld_rlx64(src + tid);
        unsigned long long q1 = ld_rlx64(src + tid + 256);
        unsigned long long q2 = ld_rlx64(src + tid + 512);
        unsigned long long q3 = ld_rlx64(src + tid + 768);
        unsigned vs = 0;
        while (((tag_of(q0) ^ want) | (tag_of(q1) ^ want) |
                (tag_of(q2) ^ want) | (tag_of(q3) ^ want)) != 0u) {
            q0 = ld_rlx64(src + tid);       q1 = ld_rlx64(src + tid + 256);
            q2 = ld_rlx64(src + tid + 512); q3 = ld_rlx64(src + tid + 768);
            if (++vs > VCAP) break;
        }
        unsigned long long r0 = ld_rlx64(rp + (tid >> 3));
        unsigned long long r1 = ld_rlx64(rp + 32 + (tid >> 3));
        unsigned long long r2 = ld_rlx64(rp + 64 + (tid >> 3));
        unsigned long long r3 = ld_rlx64(rp + 96 + (tid >> 3));
        vs = 0;
        while (((tag_of(r0) ^ want) | (tag_of(r1) ^ want) |
                (tag_of(r2) ^ want) | (tag_of(r3) ^ want)) != 0u) {
            r0 = ld_rlx64(rp + (tid >> 3));      r1 = ld_rlx64(rp + 32 + (tid >> 3));
            r2 = ld_rlx64(rp + 64 + (tid >> 3)); r3 = ld_rlx64(rp + 96 + (tid >> 3));
            if (++vs > VCAP) break;
        }

        const int eidx = *end_p;
        const float x0 = __logf(val_of(q0)) + val_of(r0) + __ldg(&trans[(size_t)eidx * NTAGS + tid]);
        const float x1 = __logf(val_of(q1)) + val_of(r1) + __ldg(&trans[(size_t)eidx * NTAGS + tid + 256]);
        const float x2 = __logf(val_of(q2)) + val_of(r2) + __ldg(&trans[(size_t)eidx * NTAGS + tid + 512]);
        const float x3 = __logf(val_of(q3)) + val_of(r3) + __ldg(&trans[(size_t)eidx * NTAGS + tid + 768]);

        float mx = fmaxf(fmaxf(x0, x1), fmaxf(x2, x3));
        #pragma unroll
        for (int msk = 16; msk >= 1; msk >>= 1)
            mx = fmaxf(mx, __shfl_xor_sync(0xffffffffu, mx, msk));
        if (lane == 0) sx[w] = mx;
        __syncthreads();
        float M = sx[0];
        #pragma unroll
        for (int w2 = 1; w2 < WARPS; w2++) M = fmaxf(M, sx[w2]);

        float s = __expf(x0 - M) + __expf(x1 - M) + __expf(x2 - M) + __expf(x3 - M);
        #pragma unroll
        for (int msk = 16; msk >= 1; msk >>= 1)
            s += __shfl_xor_sync(0xffffffffu, s, msk);
        if (lane == 0) sx[16 + w] = s;
        __syncthreads();

        if (tid == 0) {
            float Ssum = sx[16];
            #pragma unroll
            for (int w2 = 1; w2 < WARPS; w2++) Ssum += sx[16 + w2];
            out[0] = __logf(Ssum) + M;
            g_gen = gen + 1;             // version tags for the next replay
        }
    }
}

extern "C" void kernel_launch(void* const* d_in, const int* in_sizes, int n_in,
                              void* d_out, int out_size)
{
    const float* unary = (const float*)d_in[0];   // [65536, 1024] f32
    const float* trans = (const float*)d_in[1];   // [1024, 1024]  f32
    const int*   sidx  = (const int*)d_in[2];     // scalar
    const int*   eidx  = (const int*)d_in[3];     // scalar
    float*       out   = (float*)d_out;           // scalar f32

    crf_kernel<<<NCTA, TPB>>>(unary, trans, sidx, eidx, out);
}

// round 13
// speedup vs baseline: 1.4259x; 1.4259x over previous
#include <cuda_runtime.h>

#define NTAGS    1024
#define NCTA     128
#define TPB      256
#define WARPS    8
#define TSTEPS   65536
#define SPIN_CAP (1u << 20)  // watchdog (~0.25s worst case), unreachable normally
#define VCAP     (1u << 16)

// Persistent device state.
// g_ab: {f32 alpha, u32 tag} packed in 8B -> one b64 load observes
//       value+readiness atomically (no fences needed anywhere).
// g_rep: one tag per producer CTA, contiguous (4 lines) -> cheap polling.
__device__ __align__(16) unsigned long long g_ab[2][NTAGS];
__device__ __align__(16) unsigned           g_rep[2][NCTA];
__device__ unsigned g_gen = 0;   // bumped once per launch (replay-safe tags)

__device__ __forceinline__ unsigned long long ld_rlx64(const unsigned long long* p) {
    unsigned long long v;
    asm volatile("ld.relaxed.gpu.global.b64 %0, [%1];" : "=l"(v) : "l"(p));
    return v;
}
__device__ __forceinline__ void st_rlx64(unsigned long long* p, unsigned long long v) {
    asm volatile("st.relaxed.gpu.global.b64 [%0], %1;" :: "l"(p), "l"(v) : "memory");
}
__device__ __forceinline__ unsigned ld_rlx32(const unsigned* p) {
    unsigned v;
    asm volatile("ld.relaxed.gpu.global.u32 %0, [%1];" : "=r"(v) : "l"(p));
    return v;
}
__device__ __forceinline__ void st_rlx32(unsigned* p, unsigned v) {
    asm volatile("st.relaxed.gpu.global.u32 [%0], %1;" :: "l"(p), "r"(v) : "memory");
}
__device__ __forceinline__ unsigned long long pack_av(float a, unsigned tag) {
    return ((unsigned long long)tag << 32) | (unsigned long long)__float_as_uint(a);
}
__device__ __forceinline__ float    val_of(unsigned long long q) { return __uint_as_float((unsigned)q); }
__device__ __forceinline__ unsigned tag_of(unsigned long long q) { return (unsigned)(q >> 32); }

// Named barrier 1: producer-side ordering. Warps 0..6 arrive (non-blocking);
// warp 7 syncs, then publishes the CTA's rep tag.
__device__ __forceinline__ void nbar_arrive() {
    asm volatile("bar.arrive 1, %0;" :: "n"(TPB) : "memory");
}
__device__ __forceinline__ void nbar_sync() {
    asm volatile("bar.sync 1, %0;" :: "n"(TPB) : "memory");
}

__global__ void __launch_bounds__(TPB, 1)
crf_kernel(const float* __restrict__ unary,
           const float* __restrict__ trans,
           const int*   __restrict__ start_p,
           const int*   __restrict__ end_p,
           float*       __restrict__ out)
{
    const int tid  = threadIdx.x;
    const int lane = tid & 31;
    const int w    = tid >> 5;           // 8 warps
    const int cta  = blockIdx.x;
    const int row  = cta * WARPS + w;    // this warp's tag row

    __shared__ float sx[NTAGS];          // exp(alpha - m); single buffer (safe:
                                         // step-t reads precede next iteration's
                                         // first __syncthreads; t+1 writes follow it)
    __shared__ float s_a[2][WARPS];      // own alpha rows, double-buffered
    __shared__ int   s_bail;             // watchdog flag

    const unsigned gen = g_gen;          // stream-ordered across graph replays
    // tag(step s) = gen*65536 + s + 1   (never 0, unique across replays)

    if (tid == 0) s_bail = 0;

    // ---- E row in registers: warp w owns row `row`, lane owns cols {lane+32k}
    float E[32];
    #pragma unroll
    for (int k = 0; k < 32; k++)
        E[k] = __expf(__ldg(&trans[(size_t)row * NTAGS + lane + 32 * k]));

    // ---- Step 0: alpha_0[i] = trans[i, start] + u_0[i] ------------------
    float u_next = 0.0f;                 // lane0-only: next step's unary
    if (lane == 0) {
        const int sidx = *start_p;
        const float a0 = __ldg(&trans[(size_t)row * NTAGS + sidx]) + __ldg(&unary[row]);
        s_a[0][w] = a0;
        s_a[1][w] = a0;                  // stands in for alpha_{-1} at t=1,2
        st_rlx64(&g_ab[0][row], pack_av(a0, gen * 65536u + 1u));
        u_next = __ldcs(&unary[(size_t)NTAGS + row]);
    }
    // order data stores (issue) before the step-0 rep publish
    if (w < WARPS - 1) nbar_arrive(); else nbar_sync();
    if (w == WARPS - 1 && lane == 0)
        st_rlx32(&g_rep[0][cta], gen * 65536u + 1u);
    __syncthreads();

    // ---- Main scan ------------------------------------------------------
    for (int t = 1; t < TSTEPS; t++) {
        const int pb = (t - 1) & 1;      // buffer holding alpha_{t-1}
        const int b  = t & 1;

        // exp-offset from alpha_{t-2}; fmax only, no MUFU on this path.
        float mm = s_a[b][0];
        #pragma unroll
        for (int r = 1; r < WARPS; r++) mm = fmaxf(mm, s_a[b][r]);
        const float m = mm + 30.0f;      // covers 2 steps of drift + spread

        const unsigned want = gen * 65536u + (unsigned)t;  // tag of step t-1

        // SPECULATIVE wide loads for ALL warps, issued before detection.
        // Fresh ones (common for laggard CTAs) skip the post-bar retry RT.
        const unsigned long long* src = g_ab[pb];
        unsigned long long q0 = ld_rlx64(src + tid);
        unsigned long long q1 = ld_rlx64(src + tid + 256);
        unsigned long long q2 = ld_rlx64(src + tid + 512);
        unsigned long long q3 = ld_rlx64(src + tid + 768);

        // NARROW poll: warp 0 spins on the 128 contiguous rep tags (4 lines).
        if (w == 0) {
            unsigned spins = 0;
            for (;;) {
                const unsigned r0 = ld_rlx32(&g_rep[pb][lane]);
                const unsigned r1 = ld_rlx32(&g_rep[pb][lane + 32]);
                const unsigned r2 = ld_rlx32(&g_rep[pb][lane + 64]);
                const unsigned r3 = ld_rlx32(&g_rep[pb][lane + 96]);
                const bool ok = ((r0 ^ want) | (r1 ^ want) |
                                 (r2 ^ want) | (r3 ^ want)) == 0u;
                if (__all_sync(0xffffffffu, ok)) break;
                if (++spins > SPIN_CAP) { s_bail = 1; break; }
            }
        }
        __syncthreads();                 // bar1: detection done; bail broadcast
        if (s_bail) break;

        // Verify speculative loads; retry only stale stragglers.
        {
            unsigned vs = 0;
            while (((tag_of(q0) ^ want) | (tag_of(q1) ^ want) |
                    (tag_of(q2) ^ want) | (tag_of(q3) ^ want)) != 0u) {
                q0 = ld_rlx64(src + tid);       q1 = ld_rlx64(src + tid + 256);
                q2 = ld_rlx64(src + tid + 512); q3 = ld_rlx64(src + tid + 768);
                if (++vs > VCAP) break;
            }
        }

        sx[tid]       = __expf(val_of(q0) - m);
        sx[tid + 256] = __expf(val_of(q1) - m);
        sx[tid + 512] = __expf(val_of(q2) - m);
        sx[tid + 768] = __expf(val_of(q3) - m);
        __syncthreads();                 // bar2: sx staged

        // Row stage: warp w computes row `row` over all 1024 cols.
        float a0 = 0.f, a1 = 0.f, a2 = 0.f, a3 = 0.f;
        #pragma unroll
        for (int k = 0; k < 32; k += 4) {
            a0 = fmaf(E[k + 0], sx[lane + 32 * (k + 0)], a0);
            a1 = fmaf(E[k + 1], sx[lane + 32 * (k + 1)], a1);
            a2 = fmaf(E[k + 2], sx[lane + 32 * (k + 2)], a2);
            a3 = fmaf(E[k + 3], sx[lane + 32 * (k + 3)], a3);
        }
        float S = (a0 + a1) + (a2 + a3);
        #pragma unroll
        for (int msk = 16; msk >= 1; msk >>= 1)
            S += __shfl_xor_sync(0xffffffffu, S, msk);

        if (lane == 0) {
            const float alpha = __logf(S) + m + u_next;
            s_a[b][w] = alpha;
            st_rlx64(&g_ab[b][row], pack_av(alpha, want + 1u));
            const int tn = (t + 1 < TSTEPS) ? t + 1 : t;
            u_next = __ldcs(&unary[(size_t)tn * NTAGS + row]);
        }
        // Producer ordering: rep publish follows all 8 data-store issues.
        if (w < WARPS - 1) nbar_arrive(); else nbar_sync();
        if (w == WARPS - 1 && lane == 0)
            st_rlx32(&g_rep[b][cta], want + 1u);
        // next iteration's bar1 provides all remaining smem ordering
    }

    // ---- Terminal logsumexp (CTA 0) -------------------------------------
    if (cta == 0) {
        const unsigned want = gen * 65536u + (unsigned)TSTEPS; // tag of step T-1
        const unsigned long long* src = g_ab[(TSTEPS - 1) & 1];
        unsigned long long q0 = ld_rlx64(src + tid);
        unsigned long long q1 = ld_rlx64(src + tid + 256);
        unsigned long long q2 = ld_rlx64(src + tid + 512);
        unsigned long long q3 = ld_rlx64(src + tid + 768);
        {
            unsigned vs = 0;
            while (((tag_of(q0) ^ want) | (tag_of(q1) ^ want) |
                    (tag_of(q2) ^ want) | (tag_of(q3) ^ want)) != 0u) {
                q0 = ld_rlx64(src + tid);       q1 = ld_rlx64(src + tid + 256);
                q2 = ld_rlx64(src + tid + 512); q3 = ld_rlx64(src + tid + 768);
                if (++vs > VCAP) break;
            }
        }

        const int eidx = *end_p;
        const float x0 = val_of(q0) + __ldg(&trans[(size_t)eidx * NTAGS + tid]);
        const float x1 = val_of(q1) + __ldg(&trans[(size_t)eidx * NTAGS + tid + 256]);
        const float x2 = val_of(q2) + __ldg(&trans[(size_t)eidx * NTAGS + tid + 512]);
        const float x3 = val_of(q3) + __ldg(&trans[(size_t)eidx * NTAGS + tid + 768]);

        float mx = fmaxf(fmaxf(x0, x1), fmaxf(x2, x3));
        #pragma unroll
        for (int msk = 16; msk >= 1; msk >>= 1)
            mx = fmaxf(mx, __shfl_xor_sync(0xffffffffu, mx, msk));
        if (lane == 0) sx[w] = mx;
        __syncthreads();
        float M = sx[0];
        #pragma unroll
        for (int w2 = 1; w2 < WARPS; w2++) M = fmaxf(M, sx[w2]);

        float s = __expf(x0 - M) + __expf(x1 - M) + __expf(x2 - M) + __expf(x3 - M);
        #pragma unroll
        for (int msk = 16; msk >= 1; msk >>= 1)
            s += __shfl_xor_sync(0xffffffffu, s, msk);
        if (lane == 0) sx[16 + w] = s;
        __syncthreads();

        if (tid == 0) {
            float Ssum = sx[16];
            #pragma unroll
            for (int w2 = 1; w2 < WARPS; w2++) Ssum += sx[16 + w2];
            out[0] = __logf(Ssum) + M;
            g_gen = gen + 1;             // version tags for the next replay
        }
    }
}

extern "C" void kernel_launch(void* const* d_in, const int* in_sizes, int n_in,
                              void* d_out, int out_size)
{
    const float* unary = (const float*)d_in[0];   // [65536, 1024] f32
    const float* trans = (const float*)d_in[1];   // [1024, 1024]  f32
    const int*   sidx  = (const int*)d_in[2];     // scalar
    const int*   eidx  = (const int*)d_in[3];     // scalar
    float*       out   = (float*)d_out;           // scalar f32

    crf_kernel<<<NCTA, TPB>>>(unary, trans, sidx, eidx, out);
}